// round 3
// baseline (speedup 1.0000x reference)
#include <cuda_runtime.h>

#define BB 32
#define TT 2048
#define DD 1024
#define CHUNK 64

// Scratch for energies (device global: no allocation allowed in kernel_launch)
__device__ float g_energies[BB * TT];

__device__ __forceinline__ float fast_tanh(float x) {
    float y;
    asm("tanh.approx.f32 %0, %1;" : "=f"(y) : "f"(x));
    return y;
}

// ---------------------------------------------------------------------------
// Kernel 1: energies[b,t] = sum_d v[d] * tanh(keys[b,t,d] + query[b,d] + wf[b,t,d])
// One 256-thread block per (b,t); each thread handles one float4 (4 elems).
// Blocks for masked t (t >= len) exit immediately -> skip ~half the HBM traffic.
// ---------------------------------------------------------------------------
__global__ void __launch_bounds__(256) energy_kernel(
    const float* __restrict__ keys,
    const float* __restrict__ query,
    const float* __restrict__ wf,
    const float* __restrict__ v,
    const int* __restrict__ lens)
{
    const int t = blockIdx.x;
    const int b = blockIdx.y;
    if (t >= __ldg(lens + b)) return;

    const size_t row = ((size_t)b * TT + t) * DD;
    const float4* k4 = reinterpret_cast<const float4*>(keys + row);
    const float4* f4 = reinterpret_cast<const float4*>(wf + row);
    const float4* q4 = reinterpret_cast<const float4*>(query + (size_t)b * DD);
    const float4* v4 = reinterpret_cast<const float4*>(v);

    const int i = threadIdx.x;  // 0..255 covers D/4 = 256 float4s
    float4 kk = k4[i];
    float4 ff = f4[i];
    float4 qq = __ldg(q4 + i);
    float4 vv = __ldg(v4 + i);

    float s = vv.x * fast_tanh(kk.x + qq.x + ff.x)
            + vv.y * fast_tanh(kk.y + qq.y + ff.y)
            + vv.z * fast_tanh(kk.z + qq.z + ff.z)
            + vv.w * fast_tanh(kk.w + qq.w + ff.w);

    // warp reduce
    #pragma unroll
    for (int o = 16; o; o >>= 1) s += __shfl_xor_sync(0xffffffffu, s, o);

    __shared__ float ssum[8];
    if ((i & 31) == 0) ssum[i >> 5] = s;
    __syncthreads();
    if (i < 8) {
        float r = ssum[i];
        #pragma unroll
        for (int o = 4; o; o >>= 1) r += __shfl_xor_sync(0x000000ffu, r, o);
        if (i == 0) g_energies[b * TT + t] = r;
    }
}

// ---------------------------------------------------------------------------
// Kernel 2: per-batch masked softmax over energies -> weights output region;
// also zeroes the context output region (d_out is poisoned by the harness).
// One block per b. Energies are resident in L2 (256 KB total).
// ---------------------------------------------------------------------------
__global__ void __launch_bounds__(256) softmax_kernel(
    const int* __restrict__ lens,
    float* __restrict__ out)
{
    const int b = blockIdx.x;
    const int len = __ldg(lens + b);
    const float* e = g_energies + b * TT;
    float* wout = out + (size_t)BB * DD + (size_t)b * TT;  // weights region
    float* cout = out + (size_t)b * DD;                    // context region

    const int tid = threadIdx.x;
    __shared__ float red[8];
    __shared__ float s_max, s_sum;

    // ---- masked max ----
    float m = -1e30f;
    for (int t = tid; t < len; t += 256) m = fmaxf(m, e[t]);
    #pragma unroll
    for (int o = 16; o; o >>= 1) m = fmaxf(m, __shfl_xor_sync(0xffffffffu, m, o));
    if ((tid & 31) == 0) red[tid >> 5] = m;
    __syncthreads();
    if (tid == 0) {
        float mm = red[0];
        #pragma unroll
        for (int j = 1; j < 8; j++) mm = fmaxf(mm, red[j]);
        s_max = mm;
    }
    __syncthreads();
    const float bm = s_max;

    // ---- exp-sum ----
    float s = 0.f;
    for (int t = tid; t < len; t += 256) s += __expf(e[t] - bm);
    #pragma unroll
    for (int o = 16; o; o >>= 1) s += __shfl_xor_sync(0xffffffffu, s, o);
    __syncthreads();  // red reuse
    if ((tid & 31) == 0) red[tid >> 5] = s;
    __syncthreads();
    if (tid == 0) {
        float ss = red[0];
        #pragma unroll
        for (int j = 1; j < 8; j++) ss += red[j];
        s_sum = ss;
    }
    __syncthreads();
    const float inv = 1.0f / s_sum;

    // ---- write weights (0 for masked t) ----
    for (int t = tid; t < TT; t += 256)
        wout[t] = (t < len) ? __expf(e[t] - bm) * inv : 0.0f;

    // ---- zero context region for kernel 3's atomics ----
    for (int i = tid; i < DD; i += 256) cout[i] = 0.0f;
}

// ---------------------------------------------------------------------------
// Kernel 3: context[b,:] = sum_t weights[b,t] * value[b,t,:]
// Grid (T/CHUNK, B). Each block accumulates a CHUNK-long t-slab over full D
// in float4 registers, then atomicAdd into context. Masked slabs exit early.
// ---------------------------------------------------------------------------
__global__ void __launch_bounds__(256) context_kernel(
    const float* __restrict__ value,
    const int* __restrict__ lens,
    float* __restrict__ out)
{
    const int b = blockIdx.y;
    const int len = __ldg(lens + b);
    const int t0 = blockIdx.x * CHUNK;
    if (t0 >= len) return;
    const int tend = min(t0 + CHUNK, len);

    __shared__ float sw[CHUNK];
    const float* wsrc = out + (size_t)BB * DD + (size_t)b * TT;
    if (threadIdx.x < CHUNK) sw[threadIdx.x] = wsrc[t0 + threadIdx.x];
    __syncthreads();

    const int i = threadIdx.x;  // 0..255 -> one float4 of D
    float4 acc = make_float4(0.f, 0.f, 0.f, 0.f);
    const float4* vb = reinterpret_cast<const float4*>(value)
                     + ((size_t)b * TT + t0) * (DD / 4);

    #pragma unroll 4
    for (int t = t0; t < tend; ++t) {
        const float w = sw[t - t0];
        float4 vv = vb[i];
        acc.x += w * vv.x;
        acc.y += w * vv.y;
        acc.z += w * vv.z;
        acc.w += w * vv.w;
        vb += DD / 4;
    }

    float* cout = out + (size_t)b * DD + i * 4;
    atomicAdd(cout + 0, acc.x);
    atomicAdd(cout + 1, acc.y);
    atomicAdd(cout + 2, acc.z);
    atomicAdd(cout + 3, acc.w);
}

// ---------------------------------------------------------------------------
extern "C" void kernel_launch(void* const* d_in, const int* in_sizes, int n_in,
                              void* d_out, int out_size)
{
    const float* keys  = (const float*)d_in[0];
    const float* value = (const float*)d_in[1];
    const float* query = (const float*)d_in[2];
    const float* wf    = (const float*)d_in[3];
    const float* v     = (const float*)d_in[4];
    const int*   lens  = (const int*)d_in[5];
    float* out = (float*)d_out;

    energy_kernel<<<dim3(TT, BB), 256>>>(keys, query, wf, v, lens);
    softmax_kernel<<<BB, 256>>>(lens, out);
    context_kernel<<<dim3(TT / CHUNK, BB), 256>>>(value, lens, out);
}

// round 4
// speedup vs baseline: 1.1433x; 1.1433x over previous
#include <cuda_runtime.h>

#define BB 32
#define TT 2048
#define DD 1024
#define CHUNK 64
#define ROWS_PER_BLK 8   // 8 warps per block, warp-per-row

// Scratch for energies (device global: no allocation allowed in kernel_launch)
__device__ float g_energies[BB * TT];

__device__ __forceinline__ float fast_tanh(float x) {
    float y;
    asm("tanh.approx.f32 %0, %1;" : "=f"(y) : "f"(x));
    return y;
}

// ---------------------------------------------------------------------------
// Kernel 1: energies[b,t] = sum_d v[d] * tanh(keys[b,t,d] + query[b,d] + wf[b,t,d])
// Warp-per-row: each warp owns one t; each lane strides 8 float4s of keys and
// 8 of wf (high MLP), reduction is warp-local shfl (no smem / barriers).
// Warps for masked t exit immediately -> skip ~half the HBM traffic.
// ---------------------------------------------------------------------------
__global__ void __launch_bounds__(256) energy_kernel(
    const float* __restrict__ keys,
    const float* __restrict__ query,
    const float* __restrict__ wf,
    const float* __restrict__ v,
    const int* __restrict__ lens)
{
    const int b    = blockIdx.y;
    const int len  = __ldg(lens + b);
    const int warp = threadIdx.x >> 5;
    const int lane = threadIdx.x & 31;
    const int t    = blockIdx.x * ROWS_PER_BLK + warp;
    if (t >= len) return;

    const size_t row = ((size_t)b * TT + t) * DD;
    const float4* k4 = reinterpret_cast<const float4*>(keys + row);
    const float4* f4 = reinterpret_cast<const float4*>(wf + row);
    const float4* q4 = reinterpret_cast<const float4*>(query + (size_t)b * DD);
    const float4* v4 = reinterpret_cast<const float4*>(v);

    float s = 0.0f;
    #pragma unroll
    for (int j = 0; j < DD / 4 / 32; ++j) {      // 8 iterations
        const int idx = lane + 32 * j;
        float4 kk = k4[idx];
        float4 ff = f4[idx];
        float4 qq = __ldg(q4 + idx);
        float4 vv = __ldg(v4 + idx);
        s += vv.x * fast_tanh(kk.x + qq.x + ff.x)
           + vv.y * fast_tanh(kk.y + qq.y + ff.y)
           + vv.z * fast_tanh(kk.z + qq.z + ff.z)
           + vv.w * fast_tanh(kk.w + qq.w + ff.w);
    }

    // warp reduce
    #pragma unroll
    for (int o = 16; o; o >>= 1) s += __shfl_xor_sync(0xffffffffu, s, o);
    if (lane == 0) g_energies[b * TT + t] = s;
}

// ---------------------------------------------------------------------------
// Kernel 2: per-batch masked softmax over energies -> weights output region;
// also zeroes the context output region (d_out is poisoned by the harness).
// One block per b. Energies are resident in L2 (256 KB total).
// ---------------------------------------------------------------------------
__global__ void __launch_bounds__(256) softmax_kernel(
    const int* __restrict__ lens,
    float* __restrict__ out)
{
    const int b = blockIdx.x;
    const int len = __ldg(lens + b);
    const float* e = g_energies + b * TT;
    float* wout = out + (size_t)BB * DD + (size_t)b * TT;  // weights region
    float* cout = out + (size_t)b * DD;                    // context region

    const int tid = threadIdx.x;
    __shared__ float red[8];
    __shared__ float s_max, s_sum;

    // ---- masked max ----
    float m = -1e30f;
    for (int t = tid; t < len; t += 256) m = fmaxf(m, e[t]);
    #pragma unroll
    for (int o = 16; o; o >>= 1) m = fmaxf(m, __shfl_xor_sync(0xffffffffu, m, o));
    if ((tid & 31) == 0) red[tid >> 5] = m;
    __syncthreads();
    if (tid == 0) {
        float mm = red[0];
        #pragma unroll
        for (int j = 1; j < 8; j++) mm = fmaxf(mm, red[j]);
        s_max = mm;
    }
    __syncthreads();
    const float bm = s_max;

    // ---- exp-sum ----
    float s = 0.f;
    for (int t = tid; t < len; t += 256) s += __expf(e[t] - bm);
    #pragma unroll
    for (int o = 16; o; o >>= 1) s += __shfl_xor_sync(0xffffffffu, s, o);
    __syncthreads();  // red reuse
    if ((tid & 31) == 0) red[tid >> 5] = s;
    __syncthreads();
    if (tid == 0) {
        float ss = red[0];
        #pragma unroll
        for (int j = 1; j < 8; j++) ss += red[j];
        s_sum = ss;
    }
    __syncthreads();
    const float inv = 1.0f / s_sum;

    // ---- write weights (0 for masked t) ----
    for (int t = tid; t < TT; t += 256)
        wout[t] = (t < len) ? __expf(e[t] - bm) * inv : 0.0f;

    // ---- zero context region for kernel 3's atomics ----
    for (int i = tid; i < DD; i += 256) cout[i] = 0.0f;
}

// ---------------------------------------------------------------------------
// Kernel 3: context[b,:] = sum_t weights[b,t] * value[b,t,:]
// Grid (T/CHUNK, B). Each block accumulates a CHUNK-long t-slab over full D
// in float4 registers, then atomicAdd into context. Masked slabs exit early.
// ---------------------------------------------------------------------------
__global__ void __launch_bounds__(256) context_kernel(
    const float* __restrict__ value,
    const int* __restrict__ lens,
    float* __restrict__ out)
{
    const int b = blockIdx.y;
    const int len = __ldg(lens + b);
    const int t0 = blockIdx.x * CHUNK;
    if (t0 >= len) return;
    const int tend = min(t0 + CHUNK, len);

    __shared__ float sw[CHUNK];
    const float* wsrc = out + (size_t)BB * DD + (size_t)b * TT;
    if (threadIdx.x < CHUNK) sw[threadIdx.x] = wsrc[t0 + threadIdx.x];
    __syncthreads();

    const int i = threadIdx.x;  // 0..255 -> one float4 of D
    float4 acc = make_float4(0.f, 0.f, 0.f, 0.f);
    const float4* vb = reinterpret_cast<const float4*>(value)
                     + ((size_t)b * TT + t0) * (DD / 4);

    #pragma unroll 8
    for (int t = t0; t < tend; ++t) {
        const float w = sw[t - t0];
        float4 vv = vb[i];
        acc.x += w * vv.x;
        acc.y += w * vv.y;
        acc.z += w * vv.z;
        acc.w += w * vv.w;
        vb += DD / 4;
    }

    float* cout = out + (size_t)b * DD + i * 4;
    atomicAdd(cout + 0, acc.x);
    atomicAdd(cout + 1, acc.y);
    atomicAdd(cout + 2, acc.z);
    atomicAdd(cout + 3, acc.w);
}

// ---------------------------------------------------------------------------
extern "C" void kernel_launch(void* const* d_in, const int* in_sizes, int n_in,
                              void* d_out, int out_size)
{
    const float* keys  = (const float*)d_in[0];
    const float* value = (const float*)d_in[1];
    const float* query = (const float*)d_in[2];
    const float* wf    = (const float*)d_in[3];
    const float* v     = (const float*)d_in[4];
    const int*   lens  = (const int*)d_in[5];
    float* out = (float*)d_out;

    energy_kernel<<<dim3(TT / ROWS_PER_BLK, BB), 256>>>(keys, query, wf, v, lens);
    softmax_kernel<<<BB, 256>>>(lens, out);
    context_kernel<<<dim3(TT / CHUNK, BB), 256>>>(value, lens, out);
}

// round 5
// speedup vs baseline: 1.1605x; 1.0150x over previous
#include <cuda_runtime.h>

#define BB 32
#define TT 2048
#define DD 1024
#define CHUNK 64
#define ROWS_PER_BLK 8   // 8 warps per block, warp-per-row

// Scratch for energies (device global: no allocation allowed in kernel_launch)
__device__ float g_energies[BB * TT];

__device__ __forceinline__ float fast_tanh(float x) {
    float y;
    asm("tanh.approx.f32 %0, %1;" : "=f"(y) : "f"(x));
    return y;
}

// ---------------------------------------------------------------------------
// Kernel 1: energies[b,t] = sum_d v[d] * tanh(keys[b,t,d] + query[b,d] + wf[b,t,d])
// Warp-per-row, explicit 8-deep load batching (4x keys + 4x wf in registers
// before any math) for guaranteed DRAM MLP; __ldcs on streamed operands so L2
// stays free for query/v/energies. Masked-row warps exit immediately.
// ---------------------------------------------------------------------------
__global__ void __launch_bounds__(256) energy_kernel(
    const float* __restrict__ keys,
    const float* __restrict__ query,
    const float* __restrict__ wf,
    const float* __restrict__ v,
    const int* __restrict__ lens)
{
    const int b    = blockIdx.y;
    const int len  = __ldg(lens + b);
    const int warp = threadIdx.x >> 5;
    const int lane = threadIdx.x & 31;
    const int t    = blockIdx.x * ROWS_PER_BLK + warp;
    if (t >= len) return;

    const size_t row = ((size_t)b * TT + t) * DD;
    const float4* k4 = reinterpret_cast<const float4*>(keys + row);
    const float4* f4 = reinterpret_cast<const float4*>(wf + row);
    const float4* q4 = reinterpret_cast<const float4*>(query + (size_t)b * DD);
    const float4* v4 = reinterpret_cast<const float4*>(v);

    float s = 0.0f;
    #pragma unroll
    for (int h = 0; h < 2; ++h) {               // two halves of the D row
        const int base = lane + h * 128;        // 128 float4s per half
        float4 kk[4], ff[4];
        #pragma unroll
        for (int j = 0; j < 4; ++j) {           // front-batched: 8 LDGs in flight
            kk[j] = __ldcs(k4 + base + 32 * j);
            ff[j] = __ldcs(f4 + base + 32 * j);
        }
        #pragma unroll
        for (int j = 0; j < 4; ++j) {
            const int idx = base + 32 * j;
            float4 qq = __ldg(q4 + idx);
            float4 vv = __ldg(v4 + idx);
            s += vv.x * fast_tanh(kk[j].x + qq.x + ff[j].x)
               + vv.y * fast_tanh(kk[j].y + qq.y + ff[j].y)
               + vv.z * fast_tanh(kk[j].z + qq.z + ff[j].z)
               + vv.w * fast_tanh(kk[j].w + qq.w + ff[j].w);
        }
    }

    // warp reduce
    #pragma unroll
    for (int o = 16; o; o >>= 1) s += __shfl_xor_sync(0xffffffffu, s, o);
    if (lane == 0) g_energies[b * TT + t] = s;
}

// ---------------------------------------------------------------------------
// Kernel 2: per-batch masked softmax over energies -> weights output region;
// also zeroes the context output region (d_out is poisoned by the harness).
// One block per b. Energies are resident in L2 (256 KB total).
// ---------------------------------------------------------------------------
__global__ void __launch_bounds__(256) softmax_kernel(
    const int* __restrict__ lens,
    float* __restrict__ out)
{
    const int b = blockIdx.x;
    const int len = __ldg(lens + b);
    const float* e = g_energies + b * TT;
    float* wout = out + (size_t)BB * DD + (size_t)b * TT;  // weights region
    float* cout = out + (size_t)b * DD;                    // context region

    const int tid = threadIdx.x;
    __shared__ float red[8];
    __shared__ float s_max, s_sum;

    // ---- masked max ----
    float m = -1e30f;
    for (int t = tid; t < len; t += 256) m = fmaxf(m, e[t]);
    #pragma unroll
    for (int o = 16; o; o >>= 1) m = fmaxf(m, __shfl_xor_sync(0xffffffffu, m, o));
    if ((tid & 31) == 0) red[tid >> 5] = m;
    __syncthreads();
    if (tid == 0) {
        float mm = red[0];
        #pragma unroll
        for (int j = 1; j < 8; j++) mm = fmaxf(mm, red[j]);
        s_max = mm;
    }
    __syncthreads();
    const float bm = s_max;

    // ---- exp-sum ----
    float s = 0.f;
    for (int t = tid; t < len; t += 256) s += __expf(e[t] - bm);
    #pragma unroll
    for (int o = 16; o; o >>= 1) s += __shfl_xor_sync(0xffffffffu, s, o);
    __syncthreads();  // red reuse
    if ((tid & 31) == 0) red[tid >> 5] = s;
    __syncthreads();
    if (tid == 0) {
        float ss = red[0];
        #pragma unroll
        for (int j = 1; j < 8; j++) ss += red[j];
        s_sum = ss;
    }
    __syncthreads();
    const float inv = 1.0f / s_sum;

    // ---- write weights (0 for masked t) ----
    for (int t = tid; t < TT; t += 256)
        wout[t] = (t < len) ? __expf(e[t] - bm) * inv : 0.0f;

    // ---- zero context region for kernel 3's atomics ----
    for (int i = tid; i < DD; i += 256) cout[i] = 0.0f;
}

// ---------------------------------------------------------------------------
// Kernel 3: context[b,:] = sum_t weights[b,t] * value[b,t,:]
// Grid (T/CHUNK, B). Each block accumulates a CHUNK-long t-slab over full D
// in float4 registers, then atomicAdd into context. Masked slabs exit early.
// ---------------------------------------------------------------------------
__global__ void __launch_bounds__(256) context_kernel(
    const float* __restrict__ value,
    const int* __restrict__ lens,
    float* __restrict__ out)
{
    const int b = blockIdx.y;
    const int len = __ldg(lens + b);
    const int t0 = blockIdx.x * CHUNK;
    if (t0 >= len) return;
    const int tend = min(t0 + CHUNK, len);

    __shared__ float sw[CHUNK];
    const float* wsrc = out + (size_t)BB * DD + (size_t)b * TT;
    if (threadIdx.x < CHUNK) sw[threadIdx.x] = wsrc[t0 + threadIdx.x];
    __syncthreads();

    const int i = threadIdx.x;  // 0..255 -> one float4 of D
    float4 acc = make_float4(0.f, 0.f, 0.f, 0.f);
    const float4* vb = reinterpret_cast<const float4*>(value)
                     + ((size_t)b * TT + t0) * (DD / 4);

    #pragma unroll 8
    for (int t = t0; t < tend; ++t) {
        const float w = sw[t - t0];
        float4 vv = __ldcs(vb + i);
        acc.x += w * vv.x;
        acc.y += w * vv.y;
        acc.z += w * vv.z;
        acc.w += w * vv.w;
        vb += DD / 4;
    }

    float* cout = out + (size_t)b * DD + i * 4;
    atomicAdd(cout + 0, acc.x);
    atomicAdd(cout + 1, acc.y);
    atomicAdd(cout + 2, acc.z);
    atomicAdd(cout + 3, acc.w);
}

// ---------------------------------------------------------------------------
extern "C" void kernel_launch(void* const* d_in, const int* in_sizes, int n_in,
                              void* d_out, int out_size)
{
    const float* keys  = (const float*)d_in[0];
    const float* value = (const float*)d_in[1];
    const float* query = (const float*)d_in[2];
    const float* wf    = (const float*)d_in[3];
    const float* v     = (const float*)d_in[4];
    const int*   lens  = (const int*)d_in[5];
    float* out = (float*)d_out;

    energy_kernel<<<dim3(TT / ROWS_PER_BLK, BB), 256>>>(keys, query, wf, v, lens);
    softmax_kernel<<<BB, 256>>>(lens, out);
    context_kernel<<<dim3(TT / CHUNK, BB), 256>>>(value, lens, out);
}